// round 10
// baseline (speedup 1.0000x reference)
#include <cuda_runtime.h>

// e3LayerNorm over irreps 128x0e+64x1o+32x2e, graph-segmented (batch sorted).
// out[i,c] = ((x[i,c]-mean[g,c]) * s) * w[c] + bias[c], s = inv-std for scalar
// (0e) cols else 1.
//
// Single-pass persistent kernel, software-pipelined: x is read from DRAM
// exactly once (768 MB total traffic = the floor; the two-pass L2-reuse
// schedule moves 1152 MB and is capped by the ~6.9 TB/s LTS fabric).
// 32 phases of 2 graphs; 148 CTAs (1/SM, all resident -> safe grid barrier).
// Iteration k interleaves, instruction-by-instruction, "normalize phase k-1
// from SMEM tile -> DRAM write" with "load phase k DRAM -> other SMEM tile +
// register stats", so read and write streams overlap in every warp. Stats
// flush is a shared tree-reduce + global reduction atomics (no shared atomics).

#define NTOT    480
#define NC4     120
#define NPAD    121          // SMEM row stride in float4 (bank-conflict pad)
#define NSCAL   128
#define NB      64
#define GG      2            // graphs per phase
#define NPHASES (NB / GG)    // 32
#define GRID    148          // 1 CTA/SM, all resident
#define THREADS 960          // 120 float4 cols x 8 row lanes
#define LANES   8
#define SROWS   48           // tile rows per buffer (expected slice ~43)
#define EPSV    1e-5f

#define TILE_F4    (SROWS * NPAD)
#define SMEM_BYTES (2 * TILE_F4 * 16 + LANES * NC4 * 16 + 16)

__device__ int      g_start[NB + 1];
__device__ float    g_sum[NB][NTOT];
__device__ float    g_sumsq[NB][NSCAL];
__device__ unsigned g_bar;

__global__ void prep_kernel() {
    int i = blockIdx.x * blockDim.x + threadIdx.x;
    if (i < NB * NTOT)  ((float*)g_sum)[i]   = 0.f;
    if (i < NB * NSCAL) ((float*)g_sumsq)[i] = 0.f;
    if (i == 0) g_bar = 0u;
}

// g_start[g] = lower_bound(batch, g). Detects int64 vs int32 batch by probing
// an odd int32 word near the end (int64 high word == 0; int32 value ~63).
__global__ void bounds_kernel(const void* __restrict__ batch_raw, int N) {
    int t = threadIdx.x;
    if (t > NB) return;
    const int* b32 = (const int*)batch_raw;
    const long long* b64 = (const long long*)batch_raw;
    int probe = (N & 1) ? (N - 2) : (N - 1);
    bool is64 = (b32[probe] < 32);
    int lo = 0, hi = N;
    while (lo < hi) {
        int mid = (lo + hi) >> 1;
        long long v = is64 ? b64[mid] : (long long)b32[mid];
        if (v < (long long)t) lo = mid + 1; else hi = mid;
    }
    g_start[t] = lo;
}

__device__ __forceinline__ void gridbar(unsigned step) {
    __syncthreads();
    if (threadIdx.x == 0) {
        __threadfence();
        atomicAdd(&g_bar, 1u);
        unsigned target = (unsigned)GRID * step;
        while (atomicAdd(&g_bar, 0u) < target) __nanosleep(64);
    }
    __syncthreads();
}

__global__ __launch_bounds__(THREADS, 1) void persist_kernel(
    const float4* __restrict__ x4,
    const float*  __restrict__ weight,
    const float*  __restrict__ bias,
    float4*       __restrict__ o4)
{
    extern __shared__ float smem[];
    float4* tA    = (float4*)smem;
    float4* tB    = tA + TILE_F4;
    float4* s_red = tB + TILE_F4;                 // [LANES][NC4]
    float*  s_nrm = (float*)(s_red + LANES * NC4); // [2]

    int t  = threadIdx.x;
    int lc = t % NC4;
    int lr = t / NC4;
    int bid = blockIdx.x;
    bool sc = (lc < 32);

    // Per-thread affine constants (column -> weight channel).
    float w4[4], bi4[4];
    #pragma unroll
    for (int k = 0; k < 4; ++k) {
        int c = lc * 4 + k;
        int ch = (c < NSCAL) ? c : (c < 320 ? 128 + (c - 128) / 3
                                            : 192 + (c - 320) / 5);
        w4[k]  = weight[ch];
        bi4[k] = (c < NSCAL) ? bias[c] : 0.f;
    }

    unsigned barStep = 0;

    // Iteration ph: normalize phase pN=ph-1 from tileN, load phase pL=ph into
    // tileL (pL absent on the final iteration).
    for (int ph = 0; ph <= NPHASES; ++ph) {
        int pN = ph - 1;
        int pL = (ph < NPHASES) ? ph : -1;
        float4* tileL = (ph & 1) ? tB : tA;
        float4* tileN = (ph & 1) ? tA : tB;

        // ---- normalize coefficients for pN's 2 graphs ----
        int na = 0, nb = 0, nBound = 0, na0 = 0;
        float4 m4a = {0,0,0,0}, m4b = {0,0,0,0};
        float sa = 1.f, sb = 1.f;
        if (pN >= 0) {
            int G0 = pN * GG;
            int s0 = g_start[G0], s1 = g_start[G0 + GG];
            long long len = (long long)(s1 - s0);
            na = s0 + (int)(len * bid / GRID);
            nb = s0 + (int)(len * (bid + 1) / GRID);
            na0 = na;
            nBound = g_start[G0 + 1];

            float invd0 = 1.f / ((float)(g_start[G0 + 1] - g_start[G0]) + 1e-12f);
            float invd1 = 1.f / ((float)(g_start[G0 + 2] - g_start[G0 + 1]) + 1e-12f);
            float4 s40 = __ldcg(((const float4*)g_sum[G0])     + lc);
            float4 s41 = __ldcg(((const float4*)g_sum[G0 + 1]) + lc);
            m4a.x = s40.x * invd0; m4a.y = s40.y * invd0;
            m4a.z = s40.z * invd0; m4a.w = s40.w * invd0;
            m4b.x = s41.x * invd1; m4b.y = s41.y * invd1;
            m4b.z = s41.z * invd1; m4b.w = s41.w * invd1;

            if (t < 32) {   // lc==t, lr==0: m4a/m4b hold these scalar means
                float4 qa = __ldcg(((const float4*)g_sumsq[G0])     + t);
                float4 qb = __ldcg(((const float4*)g_sumsq[G0 + 1]) + t);
                float v0 = (qa.x * invd0 - m4a.x * m4a.x)
                         + (qa.y * invd0 - m4a.y * m4a.y)
                         + (qa.z * invd0 - m4a.z * m4a.z)
                         + (qa.w * invd0 - m4a.w * m4a.w);
                float v1 = (qb.x * invd1 - m4b.x * m4b.x)
                         + (qb.y * invd1 - m4b.y * m4b.y)
                         + (qb.z * invd1 - m4b.z * m4b.z)
                         + (qb.w * invd1 - m4b.w * m4b.w);
                #pragma unroll
                for (int off = 16; off > 0; off >>= 1) {
                    v0 += __shfl_xor_sync(0xffffffffu, v0, off);
                    v1 += __shfl_xor_sync(0xffffffffu, v1, off);
                }
                if (t == 0) {
                    s_nrm[0] = v0 * (1.0f / NSCAL);
                    s_nrm[1] = v1 * (1.0f / NSCAL);
                }
            }
            __syncthreads();
            float inv0 = 1.f / (sqrtf(s_nrm[0]) + EPSV);
            float inv1 = 1.f / (sqrtf(s_nrm[1]) + EPSV);
            sa = sc ? inv0 : 1.f;
            sb = sc ? inv1 : 1.f;
        }

        // ---- load slice for pL ----
        int la = 0, lb = 0, lBound = 0, la0 = 0, lg0 = 0;
        float4 acc0 = {0,0,0,0}, acc1 = {0,0,0,0};
        float4 q0   = {0,0,0,0}, q1   = {0,0,0,0};
        if (pL >= 0) {
            lg0 = pL * GG;
            int s0 = g_start[lg0], s1 = g_start[lg0 + GG];
            long long len = (long long)(s1 - s0);
            la = s0 + (int)(len * bid / GRID);
            lb = s0 + (int)(len * (bid + 1) / GRID);
            la0 = la;
            lBound = g_start[lg0 + 1];
        }

        // ---- interleaved main loop ----
        int rn = na + lr, rl = la + lr;
        while (rn < nb || rl < lb) {
            float4 vl;
            bool dl = (rl < lb);
            if (dl) vl = __ldcs(&x4[rl * NC4 + lc]);     // issue DRAM read early
            if (rn < nb) {
                int i0 = rn - na0;
                float4 v = (i0 < SROWS) ? tileN[i0 * NPAD + lc]
                                        : __ldcg(&x4[rn * NC4 + lc]);
                bool in0 = (rn < nBound);
                float4 m = in0 ? m4a : m4b;
                float  s = in0 ? sa  : sb;
                float4 o;
                o.x = fmaf((v.x - m.x) * s, w4[0], bi4[0]);
                o.y = fmaf((v.y - m.y) * s, w4[1], bi4[1]);
                o.z = fmaf((v.z - m.z) * s, w4[2], bi4[2]);
                o.w = fmaf((v.w - m.w) * s, w4[3], bi4[3]);
                __stcs(&o4[rn * NC4 + lc], o);
            }
            if (dl) {
                int i0 = rl - la0;
                if (i0 < SROWS) tileL[i0 * NPAD + lc] = vl;
                if (rl < lBound) {
                    acc0.x += vl.x; acc0.y += vl.y; acc0.z += vl.z; acc0.w += vl.w;
                    if (sc) {
                        q0.x = fmaf(vl.x, vl.x, q0.x); q0.y = fmaf(vl.y, vl.y, q0.y);
                        q0.z = fmaf(vl.z, vl.z, q0.z); q0.w = fmaf(vl.w, vl.w, q0.w);
                    }
                } else {
                    acc1.x += vl.x; acc1.y += vl.y; acc1.z += vl.z; acc1.w += vl.w;
                    if (sc) {
                        q1.x = fmaf(vl.x, vl.x, q1.x); q1.y = fmaf(vl.y, vl.y, q1.y);
                        q1.z = fmaf(vl.z, vl.z, q1.z); q1.w = fmaf(vl.w, vl.w, q1.w);
                    }
                }
            }
            rn += LANES; rl += LANES;
        }

        // ---- flush stats for pL (tree reduce, no shared atomics) ----
        if (pL >= 0) {
            __syncthreads();
            s_red[lr * NC4 + lc] = acc0;
            __syncthreads();
            if (lr == 0) {
                float4 r = s_red[lc];
                #pragma unroll
                for (int j = 1; j < LANES; ++j) {
                    float4 u = s_red[j * NC4 + lc];
                    r.x += u.x; r.y += u.y; r.z += u.z; r.w += u.w;
                }
                atomicAdd(&g_sum[lg0][lc*4+0], r.x);
                atomicAdd(&g_sum[lg0][lc*4+1], r.y);
                atomicAdd(&g_sum[lg0][lc*4+2], r.z);
                atomicAdd(&g_sum[lg0][lc*4+3], r.w);
            }
            __syncthreads();
            s_red[lr * NC4 + lc] = acc1;
            __syncthreads();
            if (lr == 0) {
                float4 r = s_red[lc];
                #pragma unroll
                for (int j = 1; j < LANES; ++j) {
                    float4 u = s_red[j * NC4 + lc];
                    r.x += u.x; r.y += u.y; r.z += u.z; r.w += u.w;
                }
                atomicAdd(&g_sum[lg0+1][lc*4+0], r.x);
                atomicAdd(&g_sum[lg0+1][lc*4+1], r.y);
                atomicAdd(&g_sum[lg0+1][lc*4+2], r.z);
                atomicAdd(&g_sum[lg0+1][lc*4+3], r.w);
            }
            __syncthreads();
            if (sc) {
                s_red[lr * NC4 + lc]      = q0;
                s_red[lr * NC4 + lc + 32] = q1;
            }
            __syncthreads();
            if (lr == 0 && lc < 64) {
                float4 r = s_red[lc];
                #pragma unroll
                for (int j = 1; j < LANES; ++j) {
                    float4 u = s_red[j * NC4 + lc];
                    r.x += u.x; r.y += u.y; r.z += u.z; r.w += u.w;
                }
                float* dst = (lc < 32) ? &g_sumsq[lg0][lc*4]
                                       : &g_sumsq[lg0+1][(lc-32)*4];
                atomicAdd(dst + 0, r.x);
                atomicAdd(dst + 1, r.y);
                atomicAdd(dst + 2, r.z);
                atomicAdd(dst + 3, r.w);
            }
            // barrier: stats(pL) globally complete before next iteration's
            // coefficient reads.
            gridbar(++barStep);
        }
    }
}

extern "C" void kernel_launch(void* const* d_in, const int* in_sizes, int n_in,
                              void* d_out, int out_size) {
    const float4* x4    = (const float4*)d_in[0];
    const float* weight = (const float*)d_in[1];
    const float* bias   = (const float*)d_in[2];
    const void*  batch  = d_in[3];
    int N = in_sizes[0] / NTOT;

    static int smem_set = 0;
    if (!smem_set) {
        cudaFuncSetAttribute(persist_kernel,
                             cudaFuncAttributeMaxDynamicSharedMemorySize,
                             SMEM_BYTES);
        smem_set = 1;
    }

    prep_kernel<<<(NB * NTOT + 255) / 256, 256>>>();
    bounds_kernel<<<1, 128>>>(batch, N);
    persist_kernel<<<GRID, THREADS, SMEM_BYTES>>>(
        x4, weight, bias, (float4*)d_out);
}

// round 14
// speedup vs baseline: 2.4936x; 2.4936x over previous
#include <cuda_runtime.h>

// e3LayerNorm over irreps 128x0e+64x1o+32x2e, graph-segmented (batch sorted).
// out[i,c] = a[g,c]*x[i,c] + b[g,c]; a/b fold mean-subtract, inv-std (scalar
// cols), weight, bias.
//
// Schedule: 8 groups of 8 contiguous graphs. In launch k, CTAs [0,288)
// normalize group k-1 (reads hit L2 from the previous launch's stats pass,
// writes stream to DRAM) while CTAs [288,432) run stats on group k (DRAM
// reads, warming L2). Split is 2:1 — proportional to bytes moved per role
// (norm: 48MB read + 48MB write; stats: 48MB read) — so role durations
// equalize and the intra-launch tail vanishes (R3's defect: occ 41%).
// Thread layout: 480 threads = 120 float4 columns x 4 row lanes; norm
// coefficients live in registers (CTA pinned to one graph).

#define NTOT     480
#define NC4      120
#define NSCAL    128
#define NB       64
#define GSZ      8
#define NGROUPS  (NB / GSZ)
#define THREADS  480
#define GRID_FUSED 432          // 3 CTAs/SM (444 slots on 148 SMs)
#define NORM_CTAS  288          // 36 CTAs/graph for norm
#define STATS_CTAS 144          // 18 CTAs/graph for stats
#define EPSV     1e-5f

__device__ int   g_start[NB + 1];
__device__ float g_sum[NB][NTOT];
__device__ float g_sumsq[NB][NSCAL];

__global__ void prep_kernel() {
    int i = blockIdx.x * blockDim.x + threadIdx.x;
    if (i < NB * NTOT)  ((float*)g_sum)[i]   = 0.f;
    if (i < NB * NSCAL) ((float*)g_sumsq)[i] = 0.f;
}

// g_start[g] = lower_bound(batch, g); handles int64 or int32 batch (probe an
// odd int32 word near the end: int64 high word == 0, int32 value ~63).
__global__ void bounds_kernel(const void* __restrict__ batch_raw, int N) {
    int t = threadIdx.x;
    if (t > NB) return;
    const int* b32 = (const int*)batch_raw;
    const long long* b64 = (const long long*)batch_raw;
    int probe = (N & 1) ? (N - 2) : (N - 1);
    bool is64 = (b32[probe] < 32);
    int lo = 0, hi = N;
    while (lo < hi) {
        int mid = (lo + hi) >> 1;
        long long v = is64 ? b64[mid] : (long long)b32[mid];
        if (v < (long long)t) lo = mid + 1; else hi = mid;
    }
    g_start[t] = lo;
}

__device__ __forceinline__ void slice(int G, int sub, int cpg, int& r0, int& r1) {
    int gs0 = g_start[G], gs1 = g_start[G + 1];
    long long len = (long long)(gs1 - gs0);
    r0 = gs0 + (int)(len * sub / cpg);
    r1 = gs0 + (int)(len * (sub + 1) / cpg);
}

__device__ __forceinline__ void acc4(float4& a, float4& q, const float4 v, bool sc) {
    a.x += v.x; a.y += v.y; a.z += v.z; a.w += v.w;
    if (sc) {
        q.x = fmaf(v.x, v.x, q.x); q.y = fmaf(v.y, v.y, q.y);
        q.z = fmaf(v.z, v.z, q.z); q.w = fmaf(v.w, v.w, q.w);
    }
}

__device__ void do_stats(const float4* __restrict__ x4, int group, int idx, int cpg) {
    __shared__ float4 s_s[4][NC4];
    __shared__ float4 s_q[4][32];

    int t = threadIdx.x, lc = t % NC4, lr = t / NC4;
    int G = group * GSZ + idx / cpg;
    int r0, r1; slice(G, idx % cpg, cpg, r0, r1);

    float4 a0 = {0,0,0,0}, a1 = {0,0,0,0};
    float4 q0 = {0,0,0,0}, q1 = {0,0,0,0};
    bool sc = (lc < 32);

    int r = r0 + lr;
    for (; r + 12 < r1; r += 16) {
        int i0 = r * NC4 + lc;
        float4 v0 = x4[i0];
        float4 v1 = x4[i0 + 4 * NC4];
        float4 v2 = x4[i0 + 8 * NC4];
        float4 v3 = x4[i0 + 12 * NC4];
        acc4(a0, q0, v0, sc); acc4(a1, q1, v1, sc);
        acc4(a0, q0, v2, sc); acc4(a1, q1, v3, sc);
    }
    for (; r < r1; r += 4)
        acc4(a0, q0, x4[r * NC4 + lc], sc);

    a0.x += a1.x; a0.y += a1.y; a0.z += a1.z; a0.w += a1.w;
    q0.x += q1.x; q0.y += q1.y; q0.z += q1.z; q0.w += q1.w;

    s_s[lr][lc] = a0;
    if (sc) s_q[lr][lc] = q0;
    __syncthreads();
    if (lr == 0) {
        float4 t0 = s_s[0][lc], t1 = s_s[1][lc], t2 = s_s[2][lc], t3 = s_s[3][lc];
        atomicAdd(&g_sum[G][lc*4+0], t0.x + t1.x + t2.x + t3.x);
        atomicAdd(&g_sum[G][lc*4+1], t0.y + t1.y + t2.y + t3.y);
        atomicAdd(&g_sum[G][lc*4+2], t0.z + t1.z + t2.z + t3.z);
        atomicAdd(&g_sum[G][lc*4+3], t0.w + t1.w + t2.w + t3.w);
        if (sc) {
            float4 u0 = s_q[0][lc], u1 = s_q[1][lc], u2 = s_q[2][lc], u3 = s_q[3][lc];
            atomicAdd(&g_sumsq[G][lc*4+0], u0.x + u1.x + u2.x + u3.x);
            atomicAdd(&g_sumsq[G][lc*4+1], u0.y + u1.y + u2.y + u3.y);
            atomicAdd(&g_sumsq[G][lc*4+2], u0.z + u1.z + u2.z + u3.z);
            atomicAdd(&g_sumsq[G][lc*4+3], u0.w + u1.w + u2.w + u3.w);
        }
    }
}

__device__ __forceinline__ int ch_of(int c) {
    return (c < NSCAL) ? c : (c < 320 ? 128 + (c - 128) / 3
                                      : 192 + (c - 320) / 5);
}

__device__ __forceinline__ float4 fma4(const float4 v, const float4 a, const float4 b) {
    float4 o;
    o.x = fmaf(v.x, a.x, b.x); o.y = fmaf(v.y, a.y, b.y);
    o.z = fmaf(v.z, a.z, b.z); o.w = fmaf(v.w, a.w, b.w);
    return o;
}

__device__ void do_norm(const float4* __restrict__ x4,
                        const float* __restrict__ weight,
                        const float* __restrict__ bias,
                        float4* __restrict__ o4, int group, int idx, int cpg) {
    __shared__ float s_norm;

    int t = threadIdx.x, lc = t % NC4, lr = t / NC4;
    int G = group * GSZ + idx / cpg;
    int r0, r1; slice(G, idx % cpg, cpg, r0, r1);

    float inv_d = 1.0f / ((float)(g_start[G + 1] - g_start[G]) + 1e-12f);

    const float4* gsum4 = (const float4*)g_sum[G];
    float4 s4 = gsum4[lc];
    float4 mean4;
    mean4.x = s4.x * inv_d; mean4.y = s4.y * inv_d;
    mean4.z = s4.z * inv_d; mean4.w = s4.w * inv_d;

    if (t < 32) {   // lc==t, lr==0 -> mean4 holds these scalar means
        const float4* gsq4 = (const float4*)g_sumsq[G];
        float4 q = gsq4[t];
        float v = (q.x * inv_d - mean4.x * mean4.x)
                + (q.y * inv_d - mean4.y * mean4.y)
                + (q.z * inv_d - mean4.z * mean4.z)
                + (q.w * inv_d - mean4.w * mean4.w);
        #pragma unroll
        for (int off = 16; off > 0; off >>= 1)
            v += __shfl_xor_sync(0xffffffffu, v, off);
        if (t == 0) s_norm = v * (1.0f / NSCAL);
    }
    __syncthreads();
    float inv = 1.0f / (sqrtf(s_norm) + EPSV);

    float4 a4, b4;
    {
        float* mp = (float*)&mean4;
        float* ap = (float*)&a4;
        float* bp = (float*)&b4;
        #pragma unroll
        for (int k = 0; k < 4; ++k) {
            int c = lc * 4 + k;
            float w = weight[ch_of(c)];
            if (c < NSCAL) { ap[k] = w * inv; bp[k] = bias[c] - mp[k] * ap[k]; }
            else           { ap[k] = w;       bp[k] = -mp[k] * w; }
        }
    }

    int r = r0 + lr;
    for (; r + 12 < r1; r += 16) {
        int i0 = r * NC4 + lc;
        float4 v0 = __ldcs(&x4[i0]);
        float4 v1 = __ldcs(&x4[i0 + 4 * NC4]);
        float4 v2 = __ldcs(&x4[i0 + 8 * NC4]);
        float4 v3 = __ldcs(&x4[i0 + 12 * NC4]);
        __stcs(&o4[i0],            fma4(v0, a4, b4));
        __stcs(&o4[i0 + 4 * NC4],  fma4(v1, a4, b4));
        __stcs(&o4[i0 + 8 * NC4],  fma4(v2, a4, b4));
        __stcs(&o4[i0 + 12 * NC4], fma4(v3, a4, b4));
    }
    for (; r < r1; r += 4) {
        int i0 = r * NC4 + lc;
        __stcs(&o4[i0], fma4(__ldcs(&x4[i0]), a4, b4));
    }
}

// Dual-role fused kernel, 2:1 CTA split matched to per-role traffic.
// Either group may be -1 (role absent -> whole grid runs the other role).
__global__ __launch_bounds__(THREADS) void fused_kernel(
    const float4* __restrict__ x4,
    const float* __restrict__ weight,
    const float* __restrict__ bias,
    float4* __restrict__ o4,
    int normGroup, int statsGroup)
{
    bool haveNorm = (normGroup >= 0), haveStats = (statsGroup >= 0);
    int nNorm = haveNorm ? (haveStats ? NORM_CTAS : GRID_FUSED) : 0;
    if ((int)blockIdx.x < nNorm) {
        do_norm(x4, weight, bias, o4, normGroup, blockIdx.x, nNorm / GSZ);
    } else if (haveStats) {
        int idx = blockIdx.x - nNorm;
        do_stats(x4, statsGroup, idx, (GRID_FUSED - nNorm) / GSZ);
    }
}

extern "C" void kernel_launch(void* const* d_in, const int* in_sizes, int n_in,
                              void* d_out, int out_size) {
    const float4* x4    = (const float4*)d_in[0];
    const float* weight = (const float*)d_in[1];
    const float* bias   = (const float*)d_in[2];
    const void*  batch  = d_in[3];
    int N = in_sizes[0] / NTOT;

    prep_kernel<<<(NB * NTOT + 255) / 256, 256>>>();
    bounds_kernel<<<1, 128>>>(batch, N);

    float4* o4 = (float4*)d_out;
    fused_kernel<<<GRID_FUSED, THREADS>>>(x4, weight, bias, o4, -1, 0);
    for (int p = 0; p < NGROUPS - 1; ++p)
        fused_kernel<<<GRID_FUSED, THREADS>>>(x4, weight, bias, o4, p, p + 1);
    fused_kernel<<<GRID_FUSED, THREADS>>>(x4, weight, bias, o4, NGROUPS - 1, -1);
}